// round 9
// baseline (speedup 1.0000x reference)
#include <cuda_runtime.h>
#include <cstdint>

// Aggregator: masked mean of sampled neighbor features.
//  d_in[0] features:      [N, 128] float32
//  d_in[1] neighbor_idx:  [N, 16]  int32
//  d_in[2] neighbor_mask: [N, 16]  int32 (0/1)
//  d_out   out:           [N, 128] float32
//
// One warp per node; lane l owns float4 columns [4l, 4l+4).
// __launch_bounds__(256,3) raises the register budget so two 8-deep batches
// of predicated LDG.128.CG (L2-only, no L1 fill) actually materialize ->
// ~8 outstanding gathers per warp, 24 warps/SM. Pre-zeroed dests + @P load
// (no select). Output stored with STG.CG (write-once, no L1 allocate).
// Accumulation via packed f32x2 adds.

#define S 16
#define D 128

__device__ __forceinline__ unsigned long long addx2(unsigned long long a, unsigned long long b) {
    unsigned long long r;
    asm("add.rn.f32x2 %0, %1, %2;" : "=l"(r) : "l"(a), "l"(b));
    return r;
}

__global__ __launch_bounds__(256, 3) void agg_kernel(
    const float* __restrict__ feat,
    const int* __restrict__ nidx,
    const int* __restrict__ mask,
    float* __restrict__ out,
    int n)
{
    int warp = (int)((blockIdx.x * (unsigned)blockDim.x + threadIdx.x) >> 5);
    int lane = threadIdx.x & 31;
    if (warp >= n) return;

    // ---- 16 int32 mask values as 4x int4 (uniform across warp) ----
    const int4* mp = reinterpret_cast<const int4*>(mask + (size_t)warp * S);
    unsigned nz = 0;
#pragma unroll
    for (int q = 0; q < 4; q++) {
        int4 m = __ldg(mp + q);
        nz |= (unsigned)(m.x != 0) << (4 * q + 0);
        nz |= (unsigned)(m.y != 0) << (4 * q + 1);
        nz |= (unsigned)(m.z != 0) << (4 * q + 2);
        nz |= (unsigned)(m.w != 0) << (4 * q + 3);
    }
    int cnt = __popc(nz);

    // ---- 16 int32 indices as 4x int4 (uniform across warp) ----
    const int4* ip = reinterpret_cast<const int4*>(nidx + (size_t)warp * S);
    int idx[S];
#pragma unroll
    for (int q = 0; q < 4; q++) {
        int4 v = __ldg(ip + q);
        idx[4 * q + 0] = v.x; idx[4 * q + 1] = v.y;
        idx[4 * q + 2] = v.z; idx[4 * q + 3] = v.w;
    }

    unsigned long long aLo0 = 0ull, aHi0 = 0ull;   // bitwise 0 == (0.f, 0.f)
    unsigned long long aLo1 = 0ull, aHi1 = 0ull;

    // ---- two batches of 8 predicated L2-only gathers ----
#pragma unroll
    for (int b = 0; b < 2; b++) {
        float4 v[8];
#pragma unroll
        for (int u = 0; u < 8; u++) {
            int j = b * 8 + u;
            float4 t = make_float4(0.f, 0.f, 0.f, 0.f);
            if ((nz >> j) & 1u) {
                const float4* row =
                    reinterpret_cast<const float4*>(feat + (size_t)idx[j] * D) + lane;
                t = __ldcg(row);           // @P LDG.E.128.CG — no L1 fill, no WAR chain
            }
            v[u] = t;
        }
#pragma unroll
        for (int u = 0; u < 8; u += 2) {
            unsigned long long lo, hi;
            asm("mov.b64 %0, {%1, %2};" : "=l"(lo) : "f"(v[u].x), "f"(v[u].y));
            asm("mov.b64 %0, {%1, %2};" : "=l"(hi) : "f"(v[u].z), "f"(v[u].w));
            aLo0 = addx2(aLo0, lo); aHi0 = addx2(aHi0, hi);
            asm("mov.b64 %0, {%1, %2};" : "=l"(lo) : "f"(v[u + 1].x), "f"(v[u + 1].y));
            asm("mov.b64 %0, {%1, %2};" : "=l"(hi) : "f"(v[u + 1].z), "f"(v[u + 1].w));
            aLo1 = addx2(aLo1, lo); aHi1 = addx2(aHi1, hi);
        }
    }
    unsigned long long aLo = addx2(aLo0, aLo1);
    unsigned long long aHi = addx2(aHi0, aHi1);

    // ---- scale by 1/count and store (L2-only, write-once) ----
    float inv = 1.0f / (float)(cnt > 0 ? cnt : 1);
    float x, y, z, w;
    asm("mov.b64 {%0, %1}, %2;" : "=f"(x), "=f"(y) : "l"(aLo));
    asm("mov.b64 {%0, %1}, %2;" : "=f"(z), "=f"(w) : "l"(aHi));
    float4 r = make_float4(x * inv, y * inv, z * inv, w * inv);
    __stcg(reinterpret_cast<float4*>(out) + (size_t)warp * (D / 4) + lane, r);
}

extern "C" void kernel_launch(void* const* d_in, const int* in_sizes, int n_in,
                              void* d_out, int out_size)
{
    const float* feat = (const float*)d_in[0];
    const int*   nidx = (const int*)d_in[1];
    const int*   mask = (const int*)d_in[2];
    float*       out  = (float*)d_out;

    int n = in_sizes[1] / S;              // 100000 nodes
    int warps_per_block = 256 / 32;       // 8 warps/block
    int blocks = (n + warps_per_block - 1) / warps_per_block;
    agg_kernel<<<blocks, 256>>>(feat, nidx, mask, out, n);
}

// round 10
// speedup vs baseline: 1.2084x; 1.2084x over previous
#include <cuda_runtime.h>
#include <cstdint>

// Aggregator: masked mean of sampled neighbor features.
//  d_in[0] features:      [N, 128] float32
//  d_in[1] neighbor_idx:  [N, 16]  int32
//  d_in[2] neighbor_mask: [N, 16]  int32 (0/1)
//  d_out   out:           [N, 128] float32
//
// R5 structure (best so far: 47.3us, occ 58.9%) with two instruction-count
// cuts: packed f32x2 accumulation (2 adds per gather instead of 4 FADDs)
// and no per-gather bounds check. One warp per node; lane l owns float4
// columns [4l,4l+4). Flat fully-unrolled predicated gather loop; default
// launch bounds so ptxas keeps ~36 regs and high occupancy.

#define S 16
#define D 128

__device__ __forceinline__ unsigned long long addx2(unsigned long long a, unsigned long long b) {
    unsigned long long r;
    asm("add.rn.f32x2 %0, %1, %2;" : "=l"(r) : "l"(a), "l"(b));
    return r;
}

__global__ __launch_bounds__(256) void agg_kernel(
    const float* __restrict__ feat,
    const int* __restrict__ nidx,
    const int* __restrict__ mask,
    float* __restrict__ out,
    int n)
{
    int warp = (int)((blockIdx.x * (unsigned)blockDim.x + threadIdx.x) >> 5);
    int lane = threadIdx.x & 31;
    if (warp >= n) return;

    // ---- 16 int32 mask values as 4x int4 (uniform across warp) ----
    const int4* mp = reinterpret_cast<const int4*>(mask + (size_t)warp * S);
    unsigned nz = 0;
#pragma unroll
    for (int q = 0; q < 4; q++) {
        int4 m = __ldg(mp + q);
        nz |= (unsigned)(m.x != 0) << (4 * q + 0);
        nz |= (unsigned)(m.y != 0) << (4 * q + 1);
        nz |= (unsigned)(m.z != 0) << (4 * q + 2);
        nz |= (unsigned)(m.w != 0) << (4 * q + 3);
    }
    int cnt = __popc(nz);

    // ---- 16 int32 indices as 4x int4 (uniform across warp) ----
    const int4* ip = reinterpret_cast<const int4*>(nidx + (size_t)warp * S);
    int idx[S];
#pragma unroll
    for (int q = 0; q < 4; q++) {
        int4 v = __ldg(ip + q);
        idx[4 * q + 0] = v.x; idx[4 * q + 1] = v.y;
        idx[4 * q + 2] = v.z; idx[4 * q + 3] = v.w;
    }

    // ---- flat predicated gather-accumulate, packed f32x2 adds ----
    unsigned long long aLo = 0ull, aHi = 0ull;     // bitwise 0 == (0.f, 0.f)
#pragma unroll
    for (int j = 0; j < S; j++) {
        if ((nz >> j) & 1u) {
            const float4* row =
                reinterpret_cast<const float4*>(feat + (size_t)idx[j] * D) + lane;
            float4 v = __ldg(row);                  // 512B coalesced per warp
            unsigned long long lo, hi;
            asm("mov.b64 %0, {%1, %2};" : "=l"(lo) : "f"(v.x), "f"(v.y));
            asm("mov.b64 %0, {%1, %2};" : "=l"(hi) : "f"(v.z), "f"(v.w));
            aLo = addx2(aLo, lo);
            aHi = addx2(aHi, hi);
        }
    }

    // ---- scale by 1/count and store ----
    float inv = 1.0f / (float)(cnt > 0 ? cnt : 1);
    float x, y, z, w;
    asm("mov.b64 {%0, %1}, %2;" : "=f"(x), "=f"(y) : "l"(aLo));
    asm("mov.b64 {%0, %1}, %2;" : "=f"(z), "=f"(w) : "l"(aHi));
    float4 r = make_float4(x * inv, y * inv, z * inv, w * inv);
    reinterpret_cast<float4*>(out)[(size_t)warp * (D / 4) + lane] = r;
}

extern "C" void kernel_launch(void* const* d_in, const int* in_sizes, int n_in,
                              void* d_out, int out_size)
{
    const float* feat = (const float*)d_in[0];
    const int*   nidx = (const int*)d_in[1];
    const int*   mask = (const int*)d_in[2];
    float*       out  = (float*)d_out;

    int n = in_sizes[1] / S;              // 100000 nodes
    int warps_per_block = 256 / 32;       // 8 warps/block
    int blocks = (n + warps_per_block - 1) / warps_per_block;
    agg_kernel<<<blocks, 256>>>(feat, nidx, mask, out, n);
}